// round 1
// baseline (speedup 1.0000x reference)
#include <cuda_runtime.h>
#include <cuda_bf16.h>
#include <cstdint>

// ---------------------------------------------------------------------------
// CoAttLayer: fused co-attention on GB300.
//   B=8, C=512, H=W=32, HW=1024, R=B*HW=8192
// Pipeline:
//  1) transpose/cast x -> XT bf16 [8192,512] (row i = b*1024+hw, col c)
//  2) convert Wq|Wk -> bf16 [1024,512], bias concat [1024] f32
//  3) GEMM: QK[8192,1024] bf16 = XT @ [Wq;Wk]^T + bias (q cols 0..511, k cols 512..1023)
//  4) fused GEMM+max: pmax[i, ktile] = max_{j in ktile*128..} q_i . k_j   (68.7 GFLOP)
//  5) logits/softmax: logit[i] = (1/8)*sum_b' max_{8 tiles of b'} pmax ; softmax per batch
//  6) m[c] = (1/8192) * sum_{b,hw} x[b,c,hw]*xw[b,hw]
//  7) proto[d] = W6[d,:].m + b6[d]
//  8) out = x * proto[c]
// ---------------------------------------------------------------------------

#define RTOT 8192
#define CCH  512
#define NQK  1024
#define NKT  64      // key tiles of 128 (8 per image)

__device__ __nv_bfloat16 g_xt[RTOT * CCH];        // 8 MB
__device__ __nv_bfloat16 g_wqk[NQK * CCH];        // 1 MB
__device__ float         g_bias[NQK];
__device__ __nv_bfloat16 g_qk[RTOT * NQK];        // 16 MB
__device__ float         g_pmax[RTOT * NKT];      // 2 MB
__device__ float         g_xw[RTOT];
__device__ float         g_m[CCH];
__device__ float         g_proto[CCH];

// ---------------- 1) transpose + cast ----------------
__global__ void transpose_cast_k(const float* __restrict__ x) {
    __shared__ float s[32][33];
    int b = blockIdx.z;
    int hw0 = blockIdx.x * 32, c0 = blockIdx.y * 32;
    int tx = threadIdx.x, ty = threadIdx.y;   // 32 x 8
#pragma unroll
    for (int j = 0; j < 32; j += 8)
        s[ty + j][tx] = x[((size_t)b * CCH + (c0 + ty + j)) * 1024 + hw0 + tx];
    __syncthreads();
#pragma unroll
    for (int j = 0; j < 32; j += 8) {
        int hw = hw0 + ty + j;
        int c  = c0 + tx;
        g_xt[(size_t)(b * 1024 + hw) * CCH + c] = __float2bfloat16(s[tx][ty + j]);
    }
}

// ---------------- 2) convert weights + bias ----------------
__global__ void convw_k(const float* __restrict__ Wq, const float* __restrict__ Wk) {
    int i = blockIdx.x * 256 + threadIdx.x;   // 2*512*512 threads
    float v = (i < CCH * CCH) ? Wq[i] : Wk[i - CCH * CCH];
    g_wqk[i] = __float2bfloat16(v);
}
__global__ void bias_k(const float* __restrict__ bq, const float* __restrict__ bk) {
    int i = threadIdx.x;  // 1024
    g_bias[i] = (i < CCH) ? bq[i] : bk[i - CCH];
}

// ---------------- mma helper ----------------
__device__ __forceinline__ void mma16816(float c[4], uint32_t a0, uint32_t a1,
                                         uint32_t a2, uint32_t a3,
                                         uint32_t b0, uint32_t b1) {
    asm volatile(
        "mma.sync.aligned.m16n8k16.row.col.f32.bf16.bf16.f32 "
        "{%0,%1,%2,%3}, {%4,%5,%6,%7}, {%8,%9}, {%0,%1,%2,%3};\n"
        : "+f"(c[0]), "+f"(c[1]), "+f"(c[2]), "+f"(c[3])
        : "r"(a0), "r"(a1), "r"(a2), "r"(a3), "r"(b0), "r"(b1));
}

// ---------------- 3/4) GEMM (templated epilogue) ----------------
// A [*,K=512] row-major bf16 stride lda; B [*,512] row-major bf16 stride ldb
// (B rows are the N dimension — exactly mma .row.col).
// Block: 128x128 tile, 256 threads, 8 warps each owning a 16x128 row strip.
// EPI=0: out bf16 = acc + bias[col] -> g_qk. EPI=1: per-row max -> g_pmax.
template <int EPI>
__global__ void __launch_bounds__(256)
gemm_bf16_k(const __nv_bfloat16* __restrict__ A, int lda,
            const __nv_bfloat16* __restrict__ B, int ldb) {
    constexpr int SKP = 40;  // padded smem row stride (bf16 elems)
    __shared__ __nv_bfloat16 sA[2][128 * SKP];
    __shared__ __nv_bfloat16 sB[2][128 * SKP];

    const int tid = threadIdx.x;
    const int bx = blockIdx.x, by = blockIdx.y;
    const int rowA0 = by * 128, rowB0 = bx * 128;

    const int lr = tid >> 2, seg = tid & 3;
    const __nv_bfloat16* gA0 = A + (size_t)(rowA0 + lr) * lda + seg * 8;
    const __nv_bfloat16* gA1 = gA0 + (size_t)64 * lda;
    const __nv_bfloat16* gB0 = B + (size_t)(rowB0 + lr) * ldb + seg * 8;
    const __nv_bfloat16* gB1 = gB0 + (size_t)64 * ldb;

    uint4 ra0, ra1, rb0, rb1;

    const int lane = tid & 31, wid = tid >> 5;
    const int mrow = wid * 16 + (lane >> 2);  // row within tile for frag base
    const int kq = (lane & 3) * 2;

    float acc[16][4];
#pragma unroll
    for (int i = 0; i < 16; i++)
#pragma unroll
        for (int j = 0; j < 4; j++) acc[i][j] = 0.f;

    // prologue load
    {
        ra0 = *(const uint4*)(gA0);
        ra1 = *(const uint4*)(gA1);
        rb0 = *(const uint4*)(gB0);
        rb1 = *(const uint4*)(gB1);
        *(uint4*)&sA[0][lr * SKP + seg * 8]        = ra0;
        *(uint4*)&sA[0][(lr + 64) * SKP + seg * 8] = ra1;
        *(uint4*)&sB[0][lr * SKP + seg * 8]        = rb0;
        *(uint4*)&sB[0][(lr + 64) * SKP + seg * 8] = rb1;
    }
    __syncthreads();

    int buf = 0;
#pragma unroll 1
    for (int kc = 0; kc < 16; kc++) {
        if (kc < 15) {
            const int off = (kc + 1) * 32;
            ra0 = *(const uint4*)(gA0 + off);
            ra1 = *(const uint4*)(gA1 + off);
            rb0 = *(const uint4*)(gB0 + off);
            rb1 = *(const uint4*)(gB1 + off);
        }
#pragma unroll
        for (int kk = 0; kk < 32; kk += 16) {
            const __nv_bfloat16* pa = &sA[buf][mrow * SKP + kk + kq];
            uint32_t a0 = *(const uint32_t*)(pa);
            uint32_t a1 = *(const uint32_t*)(pa + 8 * SKP);
            uint32_t a2 = *(const uint32_t*)(pa + 8);
            uint32_t a3 = *(const uint32_t*)(pa + 8 * SKP + 8);
#pragma unroll
            for (int nf = 0; nf < 16; nf++) {
                const __nv_bfloat16* pb =
                    &sB[buf][(nf * 8 + (lane >> 2)) * SKP + kk + kq];
                uint32_t b0 = *(const uint32_t*)(pb);
                uint32_t b1 = *(const uint32_t*)(pb + 8);
                mma16816(acc[nf], a0, a1, a2, a3, b0, b1);
            }
        }
        if (kc < 15) {
            __syncthreads();
            int nb = buf ^ 1;
            *(uint4*)&sA[nb][lr * SKP + seg * 8]        = ra0;
            *(uint4*)&sA[nb][(lr + 64) * SKP + seg * 8] = ra1;
            *(uint4*)&sB[nb][lr * SKP + seg * 8]        = rb0;
            *(uint4*)&sB[nb][(lr + 64) * SKP + seg * 8] = rb1;
            __syncthreads();
            buf = nb;
        }
    }

    const int gr0 = rowA0 + mrow;
    const int gr1 = gr0 + 8;

    if (EPI == 0) {
#pragma unroll
        for (int nf = 0; nf < 16; nf++) {
            int c = bx * 128 + nf * 8 + kq;
            float bv0 = g_bias[c], bv1 = g_bias[c + 1];
            __nv_bfloat162 v0 = __floats2bfloat162_rn(acc[nf][0] + bv0, acc[nf][1] + bv1);
            __nv_bfloat162 v1 = __floats2bfloat162_rn(acc[nf][2] + bv0, acc[nf][3] + bv1);
            *(__nv_bfloat162*)&g_qk[(size_t)gr0 * NQK + c] = v0;
            *(__nv_bfloat162*)&g_qk[(size_t)gr1 * NQK + c] = v1;
        }
    } else {
        float m0 = -1e30f, m1 = -1e30f;
#pragma unroll
        for (int nf = 0; nf < 16; nf++) {
            m0 = fmaxf(m0, fmaxf(acc[nf][0], acc[nf][1]));
            m1 = fmaxf(m1, fmaxf(acc[nf][2], acc[nf][3]));
        }
        // combine across the 4 lanes sharing the same rows (lane^1, lane^2)
        m0 = fmaxf(m0, __shfl_xor_sync(0xffffffffu, m0, 1));
        m1 = fmaxf(m1, __shfl_xor_sync(0xffffffffu, m1, 1));
        m0 = fmaxf(m0, __shfl_xor_sync(0xffffffffu, m0, 2));
        m1 = fmaxf(m1, __shfl_xor_sync(0xffffffffu, m1, 2));
        if ((lane & 3) == 0) {
            g_pmax[(size_t)gr0 * NKT + bx] = m0;
            g_pmax[(size_t)gr1 * NKT + bx] = m1;
        }
    }
}

// ---------------- 5) logits + softmax (per batch row of 1024) ----------------
__global__ void softmax_k() {
    int b = blockIdx.x;       // 0..7
    int t = threadIdx.x;      // 0..1023
    const float* p = g_pmax + (size_t)(b * 1024 + t) * NKT;
    float mean = 0.f;
#pragma unroll
    for (int g = 0; g < 8; g++) {
        float mx = p[g * 8];
#pragma unroll
        for (int u = 1; u < 8; u++) mx = fmaxf(mx, p[g * 8 + u]);
        mean += mx;
    }
    // (1/8) * (1/sqrt(512))
    float logit = mean * 0.0055242717280199024f;

    __shared__ float red[32];
    float v = logit;
#pragma unroll
    for (int o = 16; o > 0; o >>= 1) v = fmaxf(v, __shfl_xor_sync(0xffffffffu, v, o));
    if ((t & 31) == 0) red[t >> 5] = v;
    __syncthreads();
    float bmax = red[0];
#pragma unroll
    for (int i = 1; i < 32; i++) bmax = fmaxf(bmax, red[i]);
    __syncthreads();

    float e = __expf(logit - bmax);
    v = e;
#pragma unroll
    for (int o = 16; o > 0; o >>= 1) v += __shfl_xor_sync(0xffffffffu, v, o);
    if ((t & 31) == 0) red[t >> 5] = v;
    __syncthreads();
    float sum = 0.f;
#pragma unroll
    for (int i = 0; i < 32; i++) sum += red[i];

    g_xw[b * 1024 + t] = e / sum;
}

// ---------------- 6) m[c] = mean_{b,hw} x*xw ----------------
__global__ void mvec_k(const float* __restrict__ x) {
    int c = blockIdx.x;  // 0..511
    int t = threadIdx.x; // 0..255
    float s = 0.f;
#pragma unroll 1
    for (int b = 0; b < 8; b++) {
        const float* xb = x + ((size_t)b * CCH + c) * 1024;
        const float* wb = g_xw + b * 1024;
        for (int hw = t; hw < 1024; hw += 256) s += xb[hw] * wb[hw];
    }
#pragma unroll
    for (int o = 16; o > 0; o >>= 1) s += __shfl_xor_sync(0xffffffffu, s, o);
    __shared__ float red[8];
    if ((t & 31) == 0) red[t >> 5] = s;
    __syncthreads();
    if (t == 0) {
        float tot = 0.f;
#pragma unroll
        for (int i = 0; i < 8; i++) tot += red[i];
        g_m[c] = tot * (1.0f / 8192.0f);
    }
}

// ---------------- 7) proto = W6 @ m + b6 ----------------
__global__ void proto_k(const float* __restrict__ W6, const float* __restrict__ b6) {
    int d = blockIdx.x;  // 0..511
    int t = threadIdx.x; // 0..127
    const float* w = W6 + (size_t)d * CCH;
    float s = 0.f;
    for (int c = t; c < CCH; c += 128) s += w[c] * g_m[c];
#pragma unroll
    for (int o = 16; o > 0; o >>= 1) s += __shfl_xor_sync(0xffffffffu, s, o);
    __shared__ float red[4];
    if ((t & 31) == 0) red[t >> 5] = s;
    __syncthreads();
    if (t == 0) {
        float tot = red[0] + red[1] + red[2] + red[3];
        g_proto[d] = tot + b6[d];
    }
}

// ---------------- 8) out = x * proto[c] ----------------
__global__ void scale_k(const float* __restrict__ x, float* __restrict__ out) {
    size_t i = (size_t)blockIdx.x * 256 + threadIdx.x;
    int c = (int)((i >> 10) & 511);
    out[i] = x[i] * g_proto[c];
}

// ---------------------------------------------------------------------------
extern "C" void kernel_launch(void* const* d_in, const int* in_sizes, int n_in,
                              void* d_out, int out_size) {
    const float* x  = (const float*)d_in[0];
    const float* Wq = (const float*)d_in[1];
    const float* bq = (const float*)d_in[2];
    const float* Wk = (const float*)d_in[3];
    const float* bk = (const float*)d_in[4];
    const float* W6 = (const float*)d_in[5];
    const float* b6 = (const float*)d_in[6];
    float* out = (float*)d_out;

    __nv_bfloat16 *p_xt, *p_wqk, *p_qk;
    cudaGetSymbolAddress((void**)&p_xt, g_xt);
    cudaGetSymbolAddress((void**)&p_wqk, g_wqk);
    cudaGetSymbolAddress((void**)&p_qk, g_qk);

    // 1) transpose/cast
    transpose_cast_k<<<dim3(32, 16, 8), dim3(32, 8)>>>(x);
    // 2) weights/bias convert
    convw_k<<<2048, 256>>>(Wq, Wk);
    bias_k<<<1, 1024>>>(bq, bk);
    // 3) QK projection GEMM: M=8192, N=1024, K=512
    gemm_bf16_k<0><<<dim3(8, 64), 256>>>(p_xt, CCH, p_wqk, CCH);
    // 4) fused attention GEMM + per-tile row max: M=8192, N=8192, K=512
    gemm_bf16_k<1><<<dim3(64, 64), 256>>>(p_qk, NQK, p_qk + CCH, NQK);
    // 5) logits + softmax
    softmax_k<<<8, 1024>>>();
    // 6) weighted channel mean
    mvec_k<<<512, 256>>>(x);
    // 7) prototype vector
    proto_k<<<512, 128>>>(W6, b6);
    // 8) final scale
    scale_k<<<16384, 256>>>(x, out);
}

// round 15
// speedup vs baseline: 1.0798x; 1.0798x over previous
#include <cuda_runtime.h>
#include <cuda_bf16.h>
#include <cstdint>

// ---------------------------------------------------------------------------
// CoAttLayer on GB300 (sm_103a) — HMMA mma.sync path (tcgen05 rejected by the
// harness's compute_103 PTX stage). Round-1 proven structure + ldmatrix
// fragment loads to relieve the L1TEX/LSU bottleneck (was 61.7% L1, 25% tensor).
//   B=8, C=512, H=W=32, HW=1024, R=B*HW=8192
// ---------------------------------------------------------------------------

#define RTOT 8192
#define CCH  512
#define NQK  1024
#define NKT  64

__device__ __nv_bfloat16 g_xt[RTOT * CCH];        // 8 MB
__device__ __nv_bfloat16 g_wqk[NQK * CCH];        // 1 MB
__device__ float         g_bias[NQK];
__device__ __nv_bfloat16 g_qk[RTOT * NQK];        // 16 MB
__device__ float         g_pmax[RTOT * NKT];      // 2 MB
__device__ float         g_xw[RTOT];
__device__ float         g_m[CCH];
__device__ float         g_proto[CCH];

// ---------------- 1) transpose + cast ----------------
__global__ void transpose_cast_k(const float* __restrict__ x) {
    __shared__ float s[32][33];
    int b = blockIdx.z;
    int hw0 = blockIdx.x * 32, c0 = blockIdx.y * 32;
    int tx = threadIdx.x, ty = threadIdx.y;   // 32 x 8
#pragma unroll
    for (int j = 0; j < 32; j += 8)
        s[ty + j][tx] = x[((size_t)b * CCH + (c0 + ty + j)) * 1024 + hw0 + tx];
    __syncthreads();
#pragma unroll
    for (int j = 0; j < 32; j += 8) {
        int hw = hw0 + ty + j;
        int c  = c0 + tx;
        g_xt[(size_t)(b * 1024 + hw) * CCH + c] = __float2bfloat16(s[tx][ty + j]);
    }
}

// ---------------- 2) convert weights + bias ----------------
__global__ void convw_k(const float* __restrict__ Wq, const float* __restrict__ Wk) {
    int i = blockIdx.x * 256 + threadIdx.x;
    float v = (i < CCH * CCH) ? Wq[i] : Wk[i - CCH * CCH];
    g_wqk[i] = __float2bfloat16(v);
}
__global__ void bias_k(const float* __restrict__ bq, const float* __restrict__ bk) {
    int i = threadIdx.x;
    g_bias[i] = (i < CCH) ? bq[i] : bk[i - CCH];
}

// ---------------- mma + ldmatrix helpers ----------------
__device__ __forceinline__ void mma16816(float c[4], uint32_t a0, uint32_t a1,
                                         uint32_t a2, uint32_t a3,
                                         uint32_t b0, uint32_t b1) {
    asm volatile(
        "mma.sync.aligned.m16n8k16.row.col.f32.bf16.bf16.f32 "
        "{%0,%1,%2,%3}, {%4,%5,%6,%7}, {%8,%9}, {%0,%1,%2,%3};\n"
        : "+f"(c[0]), "+f"(c[1]), "+f"(c[2]), "+f"(c[3])
        : "r"(a0), "r"(a1), "r"(a2), "r"(a3), "r"(b0), "r"(b1));
}
__device__ __forceinline__ void ldmx4(uint32_t& r0, uint32_t& r1, uint32_t& r2,
                                      uint32_t& r3, uint32_t saddr) {
    asm volatile("ldmatrix.sync.aligned.m8n8.x4.shared.b16 {%0,%1,%2,%3}, [%4];"
                 : "=r"(r0), "=r"(r1), "=r"(r2), "=r"(r3) : "r"(saddr));
}
__device__ __forceinline__ uint32_t smem_u32(const void* p) {
    uint32_t a;
    asm("{ .reg .u64 t; cvta.to.shared.u64 t, %1; cvt.u32.u64 %0, t; }" : "=r"(a) : "l"(p));
    return a;
}

// ---------------- 3/4) GEMM (templated epilogue) ----------------
// A [*,512] row-major bf16 stride lda; B [*,512] row-major bf16 stride ldb.
// 128x128 tile, 256 threads, 8 warps each owning a 16x128 row strip.
// Fragments via ldmatrix.x4 (1 LDSM for A + 8 LDSM for B per k16 vs 36 LDS).
// EPI=0: out bf16 = acc + bias[col] -> g_qk. EPI=1: per-row max -> g_pmax.
template <int EPI>
__global__ void __launch_bounds__(256, 2)
gemm_bf16_k(const __nv_bfloat16* __restrict__ A, int lda,
            const __nv_bfloat16* __restrict__ B, int ldb) {
    constexpr int SKP = 40;  // padded smem row stride (bf16 elems)
    __shared__ __nv_bfloat16 sA[2][128 * SKP];
    __shared__ __nv_bfloat16 sB[2][128 * SKP];

    const int tid = threadIdx.x;
    const int bx = blockIdx.x, by = blockIdx.y;
    const int rowA0 = by * 128, rowB0 = bx * 128;

    const int lr = tid >> 2, seg = tid & 3;
    const __nv_bfloat16* gA0 = A + (size_t)(rowA0 + lr) * lda + seg * 8;
    const __nv_bfloat16* gA1 = gA0 + (size_t)64 * lda;
    const __nv_bfloat16* gB0 = B + (size_t)(rowB0 + lr) * ldb + seg * 8;
    const __nv_bfloat16* gB1 = gB0 + (size_t)64 * ldb;

    uint4 ra0, ra1, rb0, rb1;

    const int lane = tid & 31, wid = tid >> 5;
    // ldmatrix addressing: group g = lane>>3 (0..3), rowsel = lane&7
    //   row offset = (g&1)*8 + rowsel ; col offset = (g>>1)*8
    const int lm_row = ((lane >> 3) & 1) * 8 + (lane & 7);
    const int lm_col = (lane >> 4) * 8;
    const uint32_t sA_base = smem_u32(&sA[0][0]);
    const uint32_t sB_base = smem_u32(&sB[0][0]);
    const uint32_t bufstep = (uint32_t)(128 * SKP * 2);  // bytes per buffer

    float acc[16][4];
#pragma unroll
    for (int i = 0; i < 16; i++)
#pragma unroll
        for (int j = 0; j < 4; j++) acc[i][j] = 0.f;

    // prologue load
    {
        ra0 = *(const uint4*)(gA0);
        ra1 = *(const uint4*)(gA1);
        rb0 = *(const uint4*)(gB0);
        rb1 = *(const uint4*)(gB1);
        *(uint4*)&sA[0][lr * SKP + seg * 8]        = ra0;
        *(uint4*)&sA[0][(lr + 64) * SKP + seg * 8] = ra1;
        *(uint4*)&sB[0][lr * SKP + seg * 8]        = rb0;
        *(uint4*)&sB[0][(lr + 64) * SKP + seg * 8] = rb1;
    }
    __syncthreads();

    int buf = 0;
#pragma unroll 1
    for (int kc = 0; kc < 16; kc++) {
        if (kc < 15) {
            const int off = (kc + 1) * 32;
            ra0 = *(const uint4*)(gA0 + off);
            ra1 = *(const uint4*)(gA1 + off);
            rb0 = *(const uint4*)(gB0 + off);
            rb1 = *(const uint4*)(gB1 + off);
        }
#pragma unroll
        for (int kk = 0; kk < 32; kk += 16) {
            // A fragment: rows wid*16 + lm_row, cols kk + lm_col
            uint32_t a0, a1, a2, a3;
            {
                uint32_t addr = sA_base + buf * bufstep +
                    (uint32_t)(((wid * 16 + lm_row) * SKP + kk + lm_col) * 2);
                ldmx4(a0, a1, a2, a3, addr);
            }
            // B fragments: 8 x4-loads covering 16 n8 fragments
#pragma unroll
            for (int nf2 = 0; nf2 < 8; nf2++) {
                uint32_t b0, b1, b2, b3;
                uint32_t addr = sB_base + buf * bufstep +
                    (uint32_t)(((nf2 * 16 + lm_row) * SKP + kk + lm_col) * 2);
                ldmx4(b0, b1, b2, b3, addr);
                mma16816(acc[nf2 * 2],     a0, a1, a2, a3, b0, b2);
                mma16816(acc[nf2 * 2 + 1], a0, a1, a2, a3, b1, b3);
            }
        }
        if (kc < 15) {
            __syncthreads();
            int nb = buf ^ 1;
            *(uint4*)&sA[nb][lr * SKP + seg * 8]        = ra0;
            *(uint4*)&sA[nb][(lr + 64) * SKP + seg * 8] = ra1;
            *(uint4*)&sB[nb][lr * SKP + seg * 8]        = rb0;
            *(uint4*)&sB[nb][(lr + 64) * SKP + seg * 8] = rb1;
            __syncthreads();
            buf = nb;
        }
    }

    const int mrow = wid * 16 + (lane >> 2);
    const int kq = (lane & 3) * 2;
    const int gr0 = rowA0 + mrow;
    const int gr1 = gr0 + 8;

    if (EPI == 0) {
#pragma unroll
        for (int nf = 0; nf < 16; nf++) {
            int c = bx * 128 + nf * 8 + kq;
            float bv0 = g_bias[c], bv1 = g_bias[c + 1];
            __nv_bfloat162 v0 = __floats2bfloat162_rn(acc[nf][0] + bv0, acc[nf][1] + bv1);
            __nv_bfloat162 v1 = __floats2bfloat162_rn(acc[nf][2] + bv0, acc[nf][3] + bv1);
            *(__nv_bfloat162*)&g_qk[(size_t)gr0 * NQK + c] = v0;
            *(__nv_bfloat162*)&g_qk[(size_t)gr1 * NQK + c] = v1;
        }
    } else {
        float m0 = -1e30f, m1 = -1e30f;
#pragma unroll
        for (int nf = 0; nf < 16; nf++) {
            m0 = fmaxf(m0, fmaxf(acc[nf][0], acc[nf][1]));
            m1 = fmaxf(m1, fmaxf(acc[nf][2], acc[nf][3]));
        }
        m0 = fmaxf(m0, __shfl_xor_sync(0xffffffffu, m0, 1));
        m1 = fmaxf(m1, __shfl_xor_sync(0xffffffffu, m1, 1));
        m0 = fmaxf(m0, __shfl_xor_sync(0xffffffffu, m0, 2));
        m1 = fmaxf(m1, __shfl_xor_sync(0xffffffffu, m1, 2));
        if ((lane & 3) == 0) {
            g_pmax[(size_t)gr0 * NKT + bx] = m0;
            g_pmax[(size_t)gr1 * NKT + bx] = m1;
        }
    }
}

// ---------------- 5) logits + softmax (per batch row of 1024) ----------------
__global__ void softmax_k() {
    int b = blockIdx.x;       // 0..7
    int t = threadIdx.x;      // 0..1023
    const float* p = g_pmax + (size_t)(b * 1024 + t) * NKT;
    float mean = 0.f;
#pragma unroll
    for (int g = 0; g < 8; g++) {
        float mx = p[g * 8];
#pragma unroll
        for (int u = 1; u < 8; u++) mx = fmaxf(mx, p[g * 8 + u]);
        mean += mx;
    }
    float logit = mean * 0.0055242717280199024f;  // (1/8)*(1/sqrt(512))

    __shared__ float red[32];
    float v = logit;
#pragma unroll
    for (int o = 16; o > 0; o >>= 1) v = fmaxf(v, __shfl_xor_sync(0xffffffffu, v, o));
    if ((t & 31) == 0) red[t >> 5] = v;
    __syncthreads();
    float bmax = red[0];
#pragma unroll
    for (int i = 1; i < 32; i++) bmax = fmaxf(bmax, red[i]);
    __syncthreads();

    float e = __expf(logit - bmax);
    v = e;
#pragma unroll
    for (int o = 16; o > 0; o >>= 1) v += __shfl_xor_sync(0xffffffffu, v, o);
    if ((t & 31) == 0) red[t >> 5] = v;
    __syncthreads();
    float sum = 0.f;
#pragma unroll
    for (int i = 0; i < 32; i++) sum += red[i];

    g_xw[b * 1024 + t] = e / sum;
}

// ---------------- 6) m[c] = mean_{b,hw} x*xw ----------------
__global__ void mvec_k(const float* __restrict__ x) {
    int c = blockIdx.x;  // 0..511
    int t = threadIdx.x; // 0..255
    float s = 0.f;
#pragma unroll 1
    for (int b = 0; b < 8; b++) {
        const float* xb = x + ((size_t)b * CCH + c) * 1024;
        const float* wb = g_xw + b * 1024;
        for (int hw = t; hw < 1024; hw += 256) s += xb[hw] * wb[hw];
    }
#pragma unroll
    for (int o = 16; o > 0; o >>= 1) s += __shfl_xor_sync(0xffffffffu, s, o);
    __shared__ float red[8];
    if ((t & 31) == 0) red[t >> 5] = s;
    __syncthreads();
    if (t == 0) {
        float tot = 0.f;
#pragma unroll
        for (int i = 0; i < 8; i++) tot += red[i];
        g_m[c] = tot * (1.0f / 8192.0f);
    }
}

// ---------------- 7) proto = W6 @ m + b6 ----------------
__global__ void proto_k(const float* __restrict__ W6, const float* __restrict__ b6) {
    int d = blockIdx.x;  // 0..511
    int t = threadIdx.x; // 0..127
    const float* w = W6 + (size_t)d * CCH;
    float s = 0.f;
    for (int c = t; c < CCH; c += 128) s += w[c] * g_m[c];
#pragma unroll
    for (int o = 16; o > 0; o >>= 1) s += __shfl_xor_sync(0xffffffffu, s, o);
    __shared__ float red[4];
    if ((t & 31) == 0) red[t >> 5] = s;
    __syncthreads();
    if (t == 0) g_proto[d] = red[0] + red[1] + red[2] + red[3] + b6[d];
}

// ---------------- 8) out = x * proto[c] ----------------
__global__ void scale_k(const float* __restrict__ x, float* __restrict__ out) {
    size_t i = (size_t)blockIdx.x * 256 + threadIdx.x;
    int c = (int)((i >> 10) & 511);
    out[i] = x[i] * g_proto[c];
}

// ---------------------------------------------------------------------------
extern "C" void kernel_launch(void* const* d_in, const int* in_sizes, int n_in,
                              void* d_out, int out_size) {
    const float* x  = (const float*)d_in[0];
    const float* Wq = (const float*)d_in[1];
    const float* bq = (const float*)d_in[2];
    const float* Wk = (const float*)d_in[3];
    const float* bk = (const float*)d_in[4];
    const float* W6 = (const float*)d_in[5];
    const float* b6 = (const float*)d_in[6];
    float* out = (float*)d_out;

    __nv_bfloat16 *p_xt, *p_wqk, *p_qk;
    cudaGetSymbolAddress((void**)&p_xt, g_xt);
    cudaGetSymbolAddress((void**)&p_wqk, g_wqk);
    cudaGetSymbolAddress((void**)&p_qk, g_qk);

    transpose_cast_k<<<dim3(32, 16, 8), dim3(32, 8)>>>(x);
    convw_k<<<2048, 256>>>(Wq, Wk);
    bias_k<<<1, 1024>>>(bq, bk);
    // QK projection: M=8192, N=1024, K=512
    gemm_bf16_k<0><<<dim3(8, 64), 256>>>(p_xt, CCH, p_wqk, CCH);
    // fused attention GEMM + per-tile row max: M=8192, N=8192, K=512
    gemm_bf16_k<1><<<dim3(64, 64), 256>>>(p_qk, NQK, p_qk + CCH, NQK);
    softmax_k<<<8, 1024>>>();
    mvec_k<<<512, 256>>>(x);
    proto_k<<<512, 128>>>(W6, b6);
    scale_k<<<16384, 256>>>(x, out);
}